// round 11
// baseline (speedup 1.0000x reference)
#include <cuda_runtime.h>
#include <cuda_bf16.h>

#define BB 64
#define NN 2048
#define DD 256
#define EPS 1e-05f

#define CHUNKS 32
#define ROWS_PER_CHUNK (NN / CHUNKS)   // 64
#define ROWS_PER_NORM 16
#define NPARTS (NN / ROWS_PER_NORM)    // 128 norm blocks per batch
#define LEAD 4                          // stats run LEAD batches ahead of norm
#define GROUP (CHUNKS + NPARTS)         // 160
#define PREAMBLE (LEAD * CHUNKS)        // 128
#define FLAG_DONE (CHUNKS + 1)          // 33

// Owned-slot partials: no zeroing, no data races.
__device__ float2 g_partial[BB * CHUNKS];
__device__ float2 g_mi[BB];
// Protocol counters. Static-init 0; each launch restores them to 0 -> graph-safe.
__device__ unsigned int g_count[BB];
__device__ unsigned int g_done[BB];

// Pipelined layout:
//   bids [0, 128):  stats for batches 0..3
//   then 64 groups of 160: [stats(batch g+4) x32][norm(batch g) x128]
// Norm(b) waits only on stats(b), dispatched >=4 groups (~640 bids) earlier ->
// flag is already set when norm(b) becomes resident (spin ~ 0), while the
// resident set always mixes stats reads with norm writes.
__global__ __launch_bounds__(256) void fused_kernel(const float* __restrict__ x,
                                                    const int* __restrict__ lengths,
                                                    const float* __restrict__ weights,
                                                    const float* __restrict__ biases,
                                                    float* __restrict__ out) {
    const int bid = blockIdx.x;

    int b, chunk = -1, part = -1;
    if (bid < PREAMBLE) {
        b = bid >> 5;                 // batches 0..3
        chunk = bid & 31;
    } else {
        const int g = (bid - PREAMBLE) / GROUP;
        const int w = (bid - PREAMBLE) - g * GROUP;
        if (w < CHUNKS) {
            b = g + LEAD;
            if (b >= BB) return;      // no-op slots in last LEAD groups
            chunk = w;
        } else {
            b = g;
            part = w - CHUNKS;
        }
    }

    if (chunk >= 0) {
        // ---------------- Stats block ----------------
        const int len = lengths[b];
        const int row0 = chunk * ROWS_PER_CHUNK;
        const int row1 = min(row0 + ROWS_PER_CHUNK, len);

        float s0 = 0.f, s1 = 0.f, s2 = 0.f, s3 = 0.f;
        float q0 = 0.f, q1 = 0.f, q2 = 0.f, q3 = 0.f;
        if (row1 > row0) {
            const float4* __restrict__ p =
                reinterpret_cast<const float4*>(x + (size_t)b * NN * DD) + (size_t)row0 * (DD / 4);
            const int nvec = (row1 - row0) * (DD / 4);
            int i = threadIdx.x;
            for (; i + 768 < nvec; i += 1024) {
                float4 a  = p[i];
                float4 v1 = p[i + 256];
                float4 v2 = p[i + 512];
                float4 v3 = p[i + 768];
                s0 += (a.x + a.y) + (a.z + a.w);
                q0 += a.x * a.x + a.y * a.y + a.z * a.z + a.w * a.w;
                s1 += (v1.x + v1.y) + (v1.z + v1.w);
                q1 += v1.x * v1.x + v1.y * v1.y + v1.z * v1.z + v1.w * v1.w;
                s2 += (v2.x + v2.y) + (v2.z + v2.w);
                q2 += v2.x * v2.x + v2.y * v2.y + v2.z * v2.z + v2.w * v2.w;
                s3 += (v3.x + v3.y) + (v3.z + v3.w);
                q3 += v3.x * v3.x + v3.y * v3.y + v3.z * v3.z + v3.w * v3.w;
            }
            for (; i < nvec; i += 256) {
                float4 a = p[i];
                s0 += (a.x + a.y) + (a.z + a.w);
                q0 += a.x * a.x + a.y * a.y + a.z * a.z + a.w * a.w;
            }
        }
        float s  = (s0 + s1) + (s2 + s3);
        float ss = (q0 + q1) + (q2 + q3);

        #pragma unroll
        for (int off = 16; off > 0; off >>= 1) {
            s  += __shfl_xor_sync(0xFFFFFFFFu, s,  off);
            ss += __shfl_xor_sync(0xFFFFFFFFu, ss, off);
        }
        __shared__ float sh_s[8], sh_ss[8];
        const int wid = threadIdx.x >> 5;
        const int lid = threadIdx.x & 31;
        if (lid == 0) { sh_s[wid] = s; sh_ss[wid] = ss; }
        __syncthreads();
        if (wid != 0) return;
        s  = (lid < 8) ? sh_s[lid]  : 0.0f;
        ss = (lid < 8) ? sh_ss[lid] : 0.0f;
        #pragma unroll
        for (int off = 4; off > 0; off >>= 1) {
            s  += __shfl_xor_sync(0xFFFFFFFFu, s,  off);
            ss += __shfl_xor_sync(0xFFFFFFFFu, ss, off);
        }
        if (lid != 0) return;

        g_partial[b * CHUNKS + chunk] = make_float2(s, ss);
        __threadfence();
        const unsigned int old = atomicAdd(&g_count[b], 1u);
        if (old == CHUNKS - 1) {
            __threadfence();
            float fs = 0.0f, fss = 0.0f;
            #pragma unroll
            for (int i = 0; i < CHUNKS; i++) {
                float2 p = __ldcg(&g_partial[b * CHUNKS + i]);
                fs += p.x; fss += p.y;
            }
            const float denom = (float)len * (float)DD;
            const float mean  = fs / denom;
            const float var   = fmaxf(fss / denom - mean * mean, 0.0f);
            g_mi[b] = make_float2(mean, 1.0f / (sqrtf(var) + EPS));
            __threadfence();
            atomicExch(&g_count[b], FLAG_DONE);  // release flag
        }
        return;
    }

    // ---------------- Norm block ----------------
    const int len = lengths[b];
    const int base = part * ROWS_PER_NORM;
    const int r = base + (threadIdx.x >> 6);
    const int c = threadIdx.x & 63;

    float4* __restrict__ op = reinterpret_cast<float4*>(out);
    const size_t bidx = (size_t)b * NN * (DD / 4) + c;
    const float4 z = make_float4(0.0f, 0.0f, 0.0f, 0.0f);

    if (base >= len) {  // fully invalid: no stats needed, pure streaming zero-fill
        #pragma unroll
        for (int k = 0; k < 4; k++)
            __stcs(&op[bidx + (size_t)(r + 4 * k) * (DD / 4)], z);
        if (threadIdx.x == 0) {
            const unsigned int d = atomicAdd(&g_done[b], 1u);
            if (d == NPARTS - 1) {            // last norm block: re-arm protocol
                atomicExch(&g_count[b], 0u);
                atomicExch(&g_done[b], 0u);
            }
        }
        return;
    }

    // Gate on this batch's stats (dispatched >= 4 groups earlier -> usually set).
    if (threadIdx.x == 0) {
        while (*(volatile unsigned int*)&g_count[b] != FLAG_DONE) __nanosleep(32);
        __threadfence();
    }
    __syncthreads();

    const float2 mi = __ldcg(&g_mi[b]);   // L2 read: avoid stale L1 line
    const float mean = mi.x, inv = mi.y;
    const float4 w  = reinterpret_cast<const float4*>(weights)[c];
    const float4 bi = reinterpret_cast<const float4*>(biases)[c];

    if (base + ROWS_PER_NORM <= len) {  // fully valid: no per-row checks
        #pragma unroll
        for (int k = 0; k < 4; k++) {
            const size_t idx = bidx + (size_t)(r + 4 * k) * (DD / 4);
            const float4 v = reinterpret_cast<const float4*>(x)[idx];
            float4 o;
            o.x = (v.x - mean) * inv * w.x + bi.x;
            o.y = (v.y - mean) * inv * w.y + bi.y;
            o.z = (v.z - mean) * inv * w.z + bi.z;
            o.w = (v.w - mean) * inv * w.w + bi.w;
            __stcs(&op[idx], o);
        }
    } else {
        // Mixed block: per-row validity.
        #pragma unroll
        for (int k = 0; k < 4; k++) {
            const int row = r + 4 * k;
            const size_t idx = bidx + (size_t)row * (DD / 4);
            if (row < len) {
                const float4 v = reinterpret_cast<const float4*>(x)[idx];
                float4 o;
                o.x = (v.x - mean) * inv * w.x + bi.x;
                o.y = (v.y - mean) * inv * w.y + bi.y;
                o.z = (v.z - mean) * inv * w.z + bi.z;
                o.w = (v.w - mean) * inv * w.w + bi.w;
                __stcs(&op[idx], o);
            } else {
                __stcs(&op[idx], z);
            }
        }
    }

    if (threadIdx.x == 0) {
        const unsigned int d = atomicAdd(&g_done[b], 1u);
        if (d == NPARTS - 1) {                // last norm block: re-arm protocol
            atomicExch(&g_count[b], 0u);
            atomicExch(&g_done[b], 0u);
        }
    }
}

extern "C" void kernel_launch(void* const* d_in, const int* in_sizes, int n_in,
                              void* d_out, int out_size) {
    const float* x        = (const float*)d_in[0];
    const int*   lengths  = (const int*)d_in[1];
    const float* weights  = (const float*)d_in[2];
    const float* biases   = (const float*)d_in[3];
    float* out = (float*)d_out;

    fused_kernel<<<PREAMBLE + BB * GROUP, 256>>>(x, lengths, weights, biases, out);
}

// round 12
// speedup vs baseline: 1.7588x; 1.7588x over previous
#include <cuda_runtime.h>
#include <cuda_bf16.h>

#define BB 64
#define NN 2048
#define DD 256
#define EPS 1e-05f

#define CHUNKS 32
#define ROWS_PER_CHUNK (NN / CHUNKS)   // 64
#define ROWS_PER_NORM 16
#define NPARTS (NN / ROWS_PER_NORM)    // 128 norm blocks per batch
#define STATS_BLOCKS (BB * CHUNKS)     // 2048
#define FLAG_DONE (CHUNKS + 1)         // 33

// Owned-slot partials: no zeroing, no data races.
__device__ float2 g_partial[BB * CHUNKS];
__device__ float2 g_mi[BB];
// Protocol counters. Static-init 0; each launch restores them to 0 -> graph-safe.
__device__ unsigned int g_count[BB];
__device__ unsigned int g_done[BB];

__global__ __launch_bounds__(256) void fused_kernel(const float* __restrict__ x,
                                                    const int* __restrict__ lengths,
                                                    const float* __restrict__ weights,
                                                    const float* __restrict__ biases,
                                                    float* __restrict__ out) {
    const int bid = blockIdx.x;

    if (bid < STATS_BLOCKS) {
        // ---------------- Stats phase (MLP=8) ----------------
        const int b = bid >> 5;       // batch
        const int chunk = bid & 31;
        const int len = lengths[b];
        const int row0 = chunk * ROWS_PER_CHUNK;
        const int row1 = min(row0 + ROWS_PER_CHUNK, len);

        float s0 = 0.f, s1 = 0.f, s2 = 0.f, s3 = 0.f;
        float q0 = 0.f, q1 = 0.f, q2 = 0.f, q3 = 0.f;
        if (row1 > row0) {
            const float4* __restrict__ p =
                reinterpret_cast<const float4*>(x + (size_t)b * NN * DD) + (size_t)row0 * (DD / 4);
            const int nvec = (row1 - row0) * (DD / 4);  // up to 4096
            int i = threadIdx.x;
            // 8 independent loads in flight per iteration (stride 2048 per iter).
            for (; i + 1792 < nvec; i += 2048) {
                float4 a0 = p[i];
                float4 a1 = p[i + 256];
                float4 a2 = p[i + 512];
                float4 a3 = p[i + 768];
                float4 a4 = p[i + 1024];
                float4 a5 = p[i + 1280];
                float4 a6 = p[i + 1536];
                float4 a7 = p[i + 1792];
                s0 += (a0.x + a0.y) + (a0.z + a0.w);
                q0 += a0.x * a0.x + a0.y * a0.y + a0.z * a0.z + a0.w * a0.w;
                s1 += (a1.x + a1.y) + (a1.z + a1.w);
                q1 += a1.x * a1.x + a1.y * a1.y + a1.z * a1.z + a1.w * a1.w;
                s2 += (a2.x + a2.y) + (a2.z + a2.w);
                q2 += a2.x * a2.x + a2.y * a2.y + a2.z * a2.z + a2.w * a2.w;
                s3 += (a3.x + a3.y) + (a3.z + a3.w);
                q3 += a3.x * a3.x + a3.y * a3.y + a3.z * a3.z + a3.w * a3.w;
                s0 += (a4.x + a4.y) + (a4.z + a4.w);
                q0 += a4.x * a4.x + a4.y * a4.y + a4.z * a4.z + a4.w * a4.w;
                s1 += (a5.x + a5.y) + (a5.z + a5.w);
                q1 += a5.x * a5.x + a5.y * a5.y + a5.z * a5.z + a5.w * a5.w;
                s2 += (a6.x + a6.y) + (a6.z + a6.w);
                q2 += a6.x * a6.x + a6.y * a6.y + a6.z * a6.z + a6.w * a6.w;
                s3 += (a7.x + a7.y) + (a7.z + a7.w);
                q3 += a7.x * a7.x + a7.y * a7.y + a7.z * a7.z + a7.w * a7.w;
            }
            for (; i + 768 < nvec; i += 1024) {
                float4 a0 = p[i];
                float4 a1 = p[i + 256];
                float4 a2 = p[i + 512];
                float4 a3 = p[i + 768];
                s0 += (a0.x + a0.y) + (a0.z + a0.w);
                q0 += a0.x * a0.x + a0.y * a0.y + a0.z * a0.z + a0.w * a0.w;
                s1 += (a1.x + a1.y) + (a1.z + a1.w);
                q1 += a1.x * a1.x + a1.y * a1.y + a1.z * a1.z + a1.w * a1.w;
                s2 += (a2.x + a2.y) + (a2.z + a2.w);
                q2 += a2.x * a2.x + a2.y * a2.y + a2.z * a2.z + a2.w * a2.w;
                s3 += (a3.x + a3.y) + (a3.z + a3.w);
                q3 += a3.x * a3.x + a3.y * a3.y + a3.z * a3.z + a3.w * a3.w;
            }
            for (; i < nvec; i += 256) {
                float4 a = p[i];
                s0 += (a.x + a.y) + (a.z + a.w);
                q0 += a.x * a.x + a.y * a.y + a.z * a.z + a.w * a.w;
            }
        }
        float s  = (s0 + s1) + (s2 + s3);
        float ss = (q0 + q1) + (q2 + q3);

        #pragma unroll
        for (int off = 16; off > 0; off >>= 1) {
            s  += __shfl_xor_sync(0xFFFFFFFFu, s,  off);
            ss += __shfl_xor_sync(0xFFFFFFFFu, ss, off);
        }
        __shared__ float sh_s[8], sh_ss[8];
        const int wid = threadIdx.x >> 5;
        const int lid = threadIdx.x & 31;
        if (lid == 0) { sh_s[wid] = s; sh_ss[wid] = ss; }
        __syncthreads();
        if (wid != 0) return;
        s  = (lid < 8) ? sh_s[lid]  : 0.0f;
        ss = (lid < 8) ? sh_ss[lid] : 0.0f;
        #pragma unroll
        for (int off = 4; off > 0; off >>= 1) {
            s  += __shfl_xor_sync(0xFFFFFFFFu, s,  off);
            ss += __shfl_xor_sync(0xFFFFFFFFu, ss, off);
        }
        if (lid != 0) return;

        g_partial[b * CHUNKS + chunk] = make_float2(s, ss);
        __threadfence();
        const unsigned int old = atomicAdd(&g_count[b], 1u);
        if (old == CHUNKS - 1) {
            __threadfence();
            float fs = 0.0f, fss = 0.0f;
            #pragma unroll
            for (int i = 0; i < CHUNKS; i++) {
                float2 p = __ldcg(&g_partial[b * CHUNKS + i]);
                fs += p.x; fss += p.y;
            }
            const float denom = (float)len * (float)DD;
            const float mean  = fs / denom;
            const float var   = fmaxf(fss / denom - mean * mean, 0.0f);
            g_mi[b] = make_float2(mean, 1.0f / (sqrtf(var) + EPS));
            __threadfence();
            atomicExch(&g_count[b], FLAG_DONE);  // release flag
        }
        return;
    }

    // ---------------- Norm phase ----------------
    const int nb = bid - STATS_BLOCKS;
    const int b = nb >> 7;        // batch
    const int part = nb & (NPARTS - 1);
    const int len = lengths[b];
    const int base = part * ROWS_PER_NORM;
    const int r = base + (threadIdx.x >> 6);
    const int c = threadIdx.x & 63;

    float4* __restrict__ op = reinterpret_cast<float4*>(out);
    const size_t bidx = (size_t)b * NN * (DD / 4) + c;
    const float4 z = make_float4(0.0f, 0.0f, 0.0f, 0.0f);

    if (base >= len) {  // fully invalid: no stats needed, pure streaming zero-fill
        #pragma unroll
        for (int k = 0; k < 4; k++)
            __stcs(&op[bidx + (size_t)(r + 4 * k) * (DD / 4)], z);
        if (threadIdx.x == 0) {
            const unsigned int d = atomicAdd(&g_done[b], 1u);
            if (d == NPARTS - 1) {            // last norm block: re-arm protocol
                atomicExch(&g_count[b], 0u);
                atomicExch(&g_done[b], 0u);
            }
        }
        return;
    }

    // Gate on this batch's stats.
    if (threadIdx.x == 0) {
        while (*(volatile unsigned int*)&g_count[b] != FLAG_DONE) __nanosleep(32);
        __threadfence();
    }
    __syncthreads();

    const float2 mi = __ldcg(&g_mi[b]);   // L2 read: avoid stale L1 line
    const float mean = mi.x, inv = mi.y;
    const float4 w  = reinterpret_cast<const float4*>(weights)[c];
    const float4 bi = reinterpret_cast<const float4*>(biases)[c];

    if (base + ROWS_PER_NORM <= len) {  // fully valid: no per-row checks
        #pragma unroll
        for (int k = 0; k < 4; k++) {
            const size_t idx = bidx + (size_t)(r + 4 * k) * (DD / 4);
            const float4 v = reinterpret_cast<const float4*>(x)[idx];
            float4 o;
            o.x = (v.x - mean) * inv * w.x + bi.x;
            o.y = (v.y - mean) * inv * w.y + bi.y;
            o.z = (v.z - mean) * inv * w.z + bi.z;
            o.w = (v.w - mean) * inv * w.w + bi.w;
            __stcs(&op[idx], o);
        }
    } else {
        // Mixed block: per-row validity.
        #pragma unroll
        for (int k = 0; k < 4; k++) {
            const int row = r + 4 * k;
            const size_t idx = bidx + (size_t)row * (DD / 4);
            if (row < len) {
                const float4 v = reinterpret_cast<const float4*>(x)[idx];
                float4 o;
                o.x = (v.x - mean) * inv * w.x + bi.x;
                o.y = (v.y - mean) * inv * w.y + bi.y;
                o.z = (v.z - mean) * inv * w.z + bi.z;
                o.w = (v.w - mean) * inv * w.w + bi.w;
                __stcs(&op[idx], o);
            } else {
                __stcs(&op[idx], z);
            }
        }
    }

    if (threadIdx.x == 0) {
        const unsigned int d = atomicAdd(&g_done[b], 1u);
        if (d == NPARTS - 1) {                // last norm block: re-arm protocol
            atomicExch(&g_count[b], 0u);
            atomicExch(&g_done[b], 0u);
        }
    }
}

extern "C" void kernel_launch(void* const* d_in, const int* in_sizes, int n_in,
                              void* d_out, int out_size) {
    const float* x        = (const float*)d_in[0];
    const int*   lengths  = (const int*)d_in[1];
    const float* weights  = (const float*)d_in[2];
    const float* biases   = (const float*)d_in[3];
    float* out = (float*)d_out;

    fused_kernel<<<STATS_BLOCKS + BB * NPARTS, 256>>>(x, lengths, weights, biases, out);
}